// round 2
// baseline (speedup 1.0000x reference)
#include <cuda_runtime.h>

#define VIEWS 512
#define DETS  512
#define H_IMG 256
#define W_IMG 256

// ---- constants (computed in double, used as float) ----
static constexpr double dPI     = 3.14159265358979323846;
static constexpr double dS2R    = 5.95;
static constexpr double dD2R    = 4.906;
static constexpr double dD_DET  = 0.0072;
static constexpr double dVIRDET = dD_DET * dS2R / (dS2R + dD2R);
static constexpr double dD_IMG  = 0.006641;
static constexpr double dD_ANG  = 2.0 * dPI / (double)VIEWS;

// scratch for filtered sinogram: rows = (b*VIEWS + v), cols = DETS
static __device__ float g_filtered[2 * VIEWS * DETS];

// ============================================================================
// Kernel 1: weight + ramp filter, exploiting the zero pattern of the ramp
// filter (nonzero only at center tap and odd offsets -> even filt indices).
//   filtered[j] = filt[511]*q[j] + sum_{i: (i-j) odd} q[i]*filt[511+i-j]
// Compressed table Ge[n] = filt[2n] (all nonzero off-center taps live at even
// indices of filt). For even j=2a: taps Ge[256+s-a] with i=2s+1.
// For odd j=2a+1: taps Ge[255+s-a] with i=2s.
// Block: 8 rows x 512 outputs, 256 threads, per-thread tile 4 rows x 4 outputs
// (same parity, a-stride 64 -> conflict-free consecutive-lane Ge reads).
// ============================================================================
__global__ __launch_bounds__(256)
void filter_kernel(const float* __restrict__ proj,
                   const float* __restrict__ w,
                   const float* __restrict__ filt) {
    __shared__ float q[8][DETS];
    __shared__ float Ge[DETS];

    const int tid  = threadIdx.x;
    const int row0 = blockIdx.x * 8;

    for (int n = tid; n < DETS; n += 256)
        Ge[n] = filt[2 * n];
    for (int idx = tid; idx < 8 * DETS; idx += 256) {
        int r = idx >> 9;
        int c = idx & (DETS - 1);
        q[r][c] = proj[(row0 + r) * DETS + c] * w[c];
    }
    __syncthreads();

    const float fc = __ldg(filt + 511);   // center tap

    const int jt   = tid & 127;   // 128 j-threads
    const int rg   = tid >> 7;    // row group 0/1
    const int pe   = jt >> 6;     // parity of j (warp-uniform)
    const int t    = jt & 63;     // a-base
    const int rowb = rg * 4;
    const int qc   = 1 - pe;          // even j reads odd i, odd j reads even i
    const int gb   = 256 - pe - t;    // Ge index base (gi = gb + s - 64c)

    float acc[4][4];
#pragma unroll
    for (int r = 0; r < 4; ++r)
#pragma unroll
        for (int c = 0; c < 4; ++c) acc[r][c] = 0.0f;

#pragma unroll 4
    for (int s = 0; s < 256; ++s) {
        const int col = 2 * s + qc;
        float qv0 = q[rowb + 0][col];   // broadcast (warp-uniform address)
        float qv1 = q[rowb + 1][col];
        float qv2 = q[rowb + 2][col];
        float qv3 = q[rowb + 3][col];
        const int gi = gb + s;
        float g0 = Ge[gi];              // consecutive lanes -> conflict-free
        float g1 = Ge[gi - 64];
        float g2 = Ge[gi - 128];
        float g3 = Ge[gi - 192];

        acc[0][0] = fmaf(qv0, g0, acc[0][0]);
        acc[0][1] = fmaf(qv0, g1, acc[0][1]);
        acc[0][2] = fmaf(qv0, g2, acc[0][2]);
        acc[0][3] = fmaf(qv0, g3, acc[0][3]);
        acc[1][0] = fmaf(qv1, g0, acc[1][0]);
        acc[1][1] = fmaf(qv1, g1, acc[1][1]);
        acc[1][2] = fmaf(qv1, g2, acc[1][2]);
        acc[1][3] = fmaf(qv1, g3, acc[1][3]);
        acc[2][0] = fmaf(qv2, g0, acc[2][0]);
        acc[2][1] = fmaf(qv2, g1, acc[2][1]);
        acc[2][2] = fmaf(qv2, g2, acc[2][2]);
        acc[2][3] = fmaf(qv2, g3, acc[2][3]);
        acc[3][0] = fmaf(qv3, g0, acc[3][0]);
        acc[3][1] = fmaf(qv3, g1, acc[3][1]);
        acc[3][2] = fmaf(qv3, g2, acc[3][2]);
        acc[3][3] = fmaf(qv3, g3, acc[3][3]);
    }

#pragma unroll
    for (int c = 0; c < 4; ++c) {
        const int a = t + 64 * c;
        const int j = 2 * a + pe;
#pragma unroll
        for (int r = 0; r < 4; ++r) {
            float v = fmaf(fc, q[rowb + r][j], acc[r][c]);
            g_filtered[(row0 + rowb + r) * DETS + j] = v;
        }
    }
}

// ============================================================================
// Kernel 2: per-view fan-beam back-projection.
// Grid: (8 y-tiles, 512 views), 256 threads (one per x column).
// Filtered rows for this view (both batches) live in shared memory.
// Output layout: out[b][v][y][x], b-stride = VIEWS*H*W.
// ============================================================================
__global__ __launch_bounds__(256)
void backproject_kernel(float* __restrict__ out) {
    __shared__ float fr[2 * DETS];

    const int tid = threadIdx.x;       // x in [0, 256)
    const int yt  = blockIdx.x;        // y-tile [0, 8)
    const int v   = blockIdx.y;        // view

    for (int idx = tid; idx < 2 * DETS; idx += 256) {
        int b = idx >> 9;
        int d = idx & (DETS - 1);
        fr[idx] = g_filtered[(b * VIEWS + v) * DETS + d];
    }

    const float beta = (float)dD_ANG * (float)v;
    float sb, cb;
    sincosf(beta, &sb, &cb);
    __syncthreads();

    const float S2R    = (float)dS2R;
    const float DIMG   = (float)dD_IMG;
    const float K      = (float)(dS2R / dVIRDET);   // S2R / VIRDET
    const float xs     = ((float)tid - 127.5f) * DIMG;

    // hoist x-dependent products
    const float S2Rmxcb = S2R - xs * cb;   // d = S2Rmxcb - ys*sb... careful sign
    const float Kxsb    = K * (xs * sb);   // t-num = K*ys*cb - Kxsb

    const int ybase = yt * 32;
    const int bstride = VIEWS * H_IMG * W_IMG;   // 33554432
    float* o0 = out + (v * H_IMG + ybase) * W_IMG + tid;

#pragma unroll 4
    for (int yy = 0; yy < 32; ++yy) {
        const int y = ybase + yy;
        const float ys = (127.5f - (float)y) * DIMG;

        const float d    = S2Rmxcb - ys * sb;           // S2R - (xs*cb + ys*sb)
        const float invd = __fdividef(1.0f, d);
        const float num  = fmaf(ys, K * cb, -Kxsb);     // K*(ys*cb - xs*sb)
        const float t    = fmaf(num, invd, 255.5f);     // u/VIRDET + 255.5
        float wg = S2R * invd;
        wg = wg * wg;

        const float fi   = floorf(t);
        const float frac = t - fi;
        const int   i0   = (int)fi;

        const float w0 = (i0 >= 0 && i0 < DETS)      ? (1.0f - frac) : 0.0f;
        const float w1 = (i0 >= -1 && i0 < DETS - 1) ? frac          : 0.0f;
        const int i0c = min(max(i0, 0), DETS - 1);
        const int i1c = min(max(i0 + 1, 0), DETS - 1);

        const float r0 = wg * fmaf(fr[i0c], w0, fr[i1c] * w1);
        const float r1 = wg * fmaf(fr[DETS + i0c], w0, fr[DETS + i1c] * w1);

        o0[0]       = r0;
        o0[bstride] = r1;
        o0 += W_IMG;
    }
}

extern "C" void kernel_launch(void* const* d_in, const int* in_sizes, int n_in,
                              void* d_out, int out_size) {
    const float* proj = (const float*)d_in[0];   // (2,1,512,512)
    const float* w    = (const float*)d_in[1];   // (1,1,1,512)
    const float* filt = (const float*)d_in[2];   // (1,1,1,1023)
    float* out = (float*)d_out;                  // (2,512,256,256)

    filter_kernel<<<128, 256>>>(proj, w, filt);
    dim3 grid(8, VIEWS);
    backproject_kernel<<<grid, 256>>>(out);
}

// round 3
// speedup vs baseline: 1.0162x; 1.0162x over previous
#include <cuda_runtime.h>

#define VIEWS 512
#define DETS  512
#define H_IMG 256
#define W_IMG 256

// ---- constants (computed in double, used as float) ----
static constexpr double dPI     = 3.14159265358979323846;
static constexpr double dS2R    = 5.95;
static constexpr double dD2R    = 4.906;
static constexpr double dD_DET  = 0.0072;
static constexpr double dVIRDET = dD_DET * dS2R / (dS2R + dD2R);
static constexpr double dD_IMG  = 0.006641;
static constexpr double dD_ANG  = 2.0 * dPI / (double)VIEWS;

// scratch for filtered sinogram: rows = (b*VIEWS + v), cols = DETS
static __device__ float g_filtered[2 * VIEWS * DETS];

// ============================================================================
// Kernel 1: weight + ramp filter.
// Ramp filter nonzero only at center tap and odd offsets (even filt indices).
//   even j=2a   : taps q[2s+1] * Ge[256+s-a]
//   odd  j=2a+1 : taps q[2s]   * Ge[255+s-a]
// where Ge[n] = filt[2n], plus center tap fc = filt[511].
// Grid: dim3(2, 128): x = j-half, y = 8-row block.  256 threads.
// Per-thread tile: 4 rows x 1 a-value x 2 parities (8 accumulators).
// q columns (2s, 2s+1) fetched as one broadcast LDS.64.
// ============================================================================
__global__ __launch_bounds__(256)
void filter_kernel(const float* __restrict__ proj,
                   const float* __restrict__ w,
                   const float* __restrict__ filt) {
    __shared__ float q[8][DETS];     // 16 KB
    __shared__ float Ge[DETS];       // 2 KB

    const int tid  = threadIdx.x;
    const int jh   = blockIdx.x;           // j-half: a in [jh*128, jh*128+128)
    const int row0 = blockIdx.y * 8;

    for (int n = tid; n < DETS; n += 256)
        Ge[n] = filt[2 * n];
    for (int idx = tid; idx < 8 * DETS; idx += 256) {
        int r = idx >> 9;
        int c = idx & (DETS - 1);
        q[r][c] = proj[(row0 + r) * DETS + c] * w[c];
    }
    __syncthreads();

    const float fc = __ldg(filt + 511);    // center tap

    const int t    = tid & 127;            // a-thread
    const int rg   = tid >> 7;             // row group (0/1)
    const int rowb = rg * 4;
    const int a    = jh * 128 + t;
    const int gib  = 256 - a;              // gi = gib + s

    float accE[4], accO[4];
#pragma unroll
    for (int r = 0; r < 4; ++r) { accE[r] = 0.0f; accO[r] = 0.0f; }

#pragma unroll 4
    for (int s = 0; s < 256; ++s) {
        float2 q0 = *(const float2*)&q[rowb + 0][2 * s];
        float2 q1 = *(const float2*)&q[rowb + 1][2 * s];
        float2 q2 = *(const float2*)&q[rowb + 2][2 * s];
        float2 q3 = *(const float2*)&q[rowb + 3][2 * s];
        const int gi = gib + s;
        const float ge = Ge[gi];        // consecutive lanes -> conflict-free
        const float go = Ge[gi - 1];

        accE[0] = fmaf(q0.y, ge, accE[0]);
        accO[0] = fmaf(q0.x, go, accO[0]);
        accE[1] = fmaf(q1.y, ge, accE[1]);
        accO[1] = fmaf(q1.x, go, accO[1]);
        accE[2] = fmaf(q2.y, ge, accE[2]);
        accO[2] = fmaf(q2.x, go, accO[2]);
        accE[3] = fmaf(q3.y, ge, accE[3]);
        accO[3] = fmaf(q3.x, go, accO[3]);
    }

    const int j = 2 * a;
#pragma unroll
    for (int r = 0; r < 4; ++r) {
        float ve = fmaf(fc, q[rowb + r][j],     accE[r]);
        float vo = fmaf(fc, q[rowb + r][j + 1], accO[r]);
        *(float2*)&g_filtered[(row0 + rowb + r) * DETS + j] = make_float2(ve, vo);
    }
}

// ============================================================================
// Kernel 2: fan-beam back-projection with half-turn symmetry.
// View pair (v, v+256): geometry (t, wgt) at pixel (x,y) for view v equals
// geometry at mirrored pixel (255-x, 255-y) for view v+256.
// Filtered rows live in smem padded to 1024 with zero borders at [0,128) and
// [640,1024): i0 in [-125,636] -> padded index = floor(t + 383.5) in [3,763].
// Zero pads make the validity masks unnecessary (0 * anything = 0).
// Grid: (8 y-tiles, 256 view-pairs), 256 threads = 128 x-pairs x 2 y-offsets.
// Stores: 4x STG.64 per iteration (2 views x 2 batches, x-pair vectorized;
// mirrored stores are component-swapped but still 8B-aligned & coalesced).
// ============================================================================
__global__ __launch_bounds__(256)
void backproject_kernel(float* __restrict__ out) {
    __shared__ float fr[4][1024];   // [vi*2 + b][padded det], 16 KB

    const int tid = threadIdx.x;
    const int tx  = tid & 127;      // x-pair index: x0 = 2tx, x1 = 2tx+1
    const int ty  = tid >> 7;       // y offset within row pair
    const int yt  = blockIdx.x;     // y-tile [0,8)
    const int vp  = blockIdx.y;     // view pair: v0 = vp, v1 = vp + 256

    for (int idx = tid; idx < 4096; idx += 256) {
        const int row = idx >> 10;
        const int col = idx & 1023;
        const int vi  = row >> 1;
        const int b   = row & 1;
        const int c   = col - 128;
        float val = 0.0f;
        if ((unsigned)c < (unsigned)DETS)
            val = g_filtered[(b * VIEWS + vp + vi * 256) * DETS + c];
        fr[row][col] = val;
    }

    const float beta = (float)dD_ANG * (float)vp;
    float sb, cb;
    sincosf(beta, &sb, &cb);
    __syncthreads();

    const float S2R  = (float)dS2R;
    const float DIMG = (float)dD_IMG;
    const float K    = (float)(dS2R / dVIRDET);
    const float Kcb  = K * cb;

    const float xs0 = (2.0f * (float)tx - 127.5f) * DIMG;
    const float xs1 = xs0 + DIMG;
    const float A0  = S2R - xs0 * cb;      // d = A - ys*sb
    const float A1  = S2R - xs1 * cb;
    const float B0  = K * (xs0 * sb);      // num = ys*Kcb - B
    const float B1  = K * (xs1 * sb);

    const int ybase = yt * 32;
    const int bstr  = VIEWS * H_IMG * W_IMG;

    float* p0 = out + ((vp)       * H_IMG + (ybase + ty))       * W_IMG + 2 * tx;
    float* pm = out + ((vp + 256) * H_IMG + (255 - ybase - ty)) * W_IMG + (254 - 2 * tx);

#pragma unroll 4
    for (int i = 0; i < 16; ++i) {
        const float yv    = (float)(ybase + 2 * i + ty);
        const float ys    = (127.5f - yv) * DIMG;
        const float yssb  = ys * sb;
        const float ysKcb = ys * Kcb;

        const float d0   = A0 - yssb;
        const float d1   = A1 - yssb;
        const float inv0 = __fdividef(1.0f, d0);
        const float inv1 = __fdividef(1.0f, d1);
        const float t0   = fmaf(ysKcb - B0, inv0, 383.5f);   // +255.5 +128 pad bias
        const float t1   = fmaf(ysKcb - B1, inv1, 383.5f);
        float wg0 = S2R * inv0; wg0 *= wg0;
        float wg1 = S2R * inv1; wg1 *= wg1;

        const float f0 = floorf(t0);
        const float f1 = floorf(t1);
        const float h0 = t0 - f0;
        const float h1 = t1 - f1;
        const int   j0 = (int)f0;
        const int   j1 = (int)f1;

        // lerp(row, j, h) = a + h*(b-a)
        float a00 = fr[0][j0], b00 = fr[0][j0 + 1];
        float a01 = fr[1][j0], b01 = fr[1][j0 + 1];
        float a02 = fr[2][j0], b02 = fr[2][j0 + 1];
        float a03 = fr[3][j0], b03 = fr[3][j0 + 1];
        float a10 = fr[0][j1], b10 = fr[0][j1 + 1];
        float a11 = fr[1][j1], b11 = fr[1][j1 + 1];
        float a12 = fr[2][j1], b12 = fr[2][j1 + 1];
        float a13 = fr[3][j1], b13 = fr[3][j1 + 1];

        const float v00x0 = wg0 * fmaf(h0, b00 - a00, a00);  // view0 b0 x0
        const float v01x0 = wg0 * fmaf(h0, b01 - a01, a01);  // view0 b1 x0
        const float v10x0 = wg0 * fmaf(h0, b02 - a02, a02);  // view1 b0 x0
        const float v11x0 = wg0 * fmaf(h0, b03 - a03, a03);  // view1 b1 x0
        const float v00x1 = wg1 * fmaf(h1, b10 - a10, a10);
        const float v01x1 = wg1 * fmaf(h1, b11 - a11, a11);
        const float v10x1 = wg1 * fmaf(h1, b12 - a12, a12);
        const float v11x1 = wg1 * fmaf(h1, b13 - a13, a13);

        *(float2*)(p0)        = make_float2(v00x0, v00x1);
        *(float2*)(p0 + bstr) = make_float2(v01x0, v01x1);
        // mirrored view: x reversed -> swap components
        *(float2*)(pm)        = make_float2(v10x1, v10x0);
        *(float2*)(pm + bstr) = make_float2(v11x1, v11x0);

        p0 += 2 * W_IMG;
        pm -= 2 * W_IMG;
    }
}

extern "C" void kernel_launch(void* const* d_in, const int* in_sizes, int n_in,
                              void* d_out, int out_size) {
    const float* proj = (const float*)d_in[0];   // (2,1,512,512)
    const float* w    = (const float*)d_in[1];   // (1,1,1,512)
    const float* filt = (const float*)d_in[2];   // (1,1,1,1023)
    float* out = (float*)d_out;                  // (2,512,256,256)

    filter_kernel<<<dim3(2, 128), 256>>>(proj, w, filt);
    backproject_kernel<<<dim3(8, 256), 256>>>(out);
}